// round 16
// baseline (speedup 1.0000x reference)
#include <cuda_runtime.h>
#include <cuda_fp16.h>
#include <cstdint>

// ---------------------------------------------------------------------------
// Problem constants:  x (4,5280,1024) fp32.  M = 21120 rows, K = 1024.
// Spatial attn: 96 seqs x 220 (tensor-core flash kernel, K/V staged once,
// internal q-block loop, 2 CTAs/SM).  Temporal attn: 880 seqs x 24 (scalar).
// GEMMs via mma.sync.m16n8k16 fp16, 128x128x64 tiles / 3-stage cp.async,
// 128 threads / 4 warps (warp tile 64x64, double-buffered frags — best
// measured config, R14).  RMSNorm+RoPE fused into QKV epilogue (fp16 out);
// s2t / t2s permutes fused into the projection epilogues.
// ---------------------------------------------------------------------------
#define MROWS 21120

// Scratch (static __device__ arrays — no allocation allowed)
__device__ __align__(1024) unsigned short g_qkv[64880640ull];   // qkv fp16
__device__ __align__(1024) float2         g_rope[7040];         // 220 x 32 (cos,sin)
__device__ __align__(1024) unsigned short g_halfX[21626880ull]; // x fp16 / temporal in
__device__ __align__(1024) unsigned short g_halfB[21626880ull]; // attn out fp16
__device__ __align__(1024) unsigned short g_halfW[8388608ull];  // weights fp16

// ---------------------------------------------------------------------------
// PTX helpers (base-target: cp.async sm_80, ldmatrix sm_75, mma sm_80)
// ---------------------------------------------------------------------------
__device__ __forceinline__ uint32_t su32(const void* p) {
    return (uint32_t)__cvta_generic_to_shared(p);
}
__device__ __forceinline__ void cp_async16(uint32_t s, const void* g) {
    asm volatile("cp.async.cg.shared.global [%0], [%1], 16;" :: "r"(s), "l"(g));
}
__device__ __forceinline__ void ldsm4(uint32_t* r, uint32_t a) {
    asm volatile("ldmatrix.sync.aligned.m8n8.x4.shared.b16 {%0,%1,%2,%3}, [%4];"
                 : "=r"(r[0]), "=r"(r[1]), "=r"(r[2]), "=r"(r[3]) : "r"(a));
}
__device__ __forceinline__ void ldsm4t(uint32_t* r, uint32_t a) {
    asm volatile("ldmatrix.sync.aligned.m8n8.x4.trans.shared.b16 {%0,%1,%2,%3}, [%4];"
                 : "=r"(r[0]), "=r"(r[1]), "=r"(r[2]), "=r"(r[3]) : "r"(a));
}
__device__ __forceinline__ void mma16816(float* c, const uint32_t* a,
                                         uint32_t b0, uint32_t b1) {
    asm volatile(
        "mma.sync.aligned.m16n8k16.row.col.f32.f16.f16.f32 "
        "{%0,%1,%2,%3}, {%4,%5,%6,%7}, {%8,%9}, {%0,%1,%2,%3};"
        : "+f"(c[0]), "+f"(c[1]), "+f"(c[2]), "+f"(c[3])
        : "r"(a[0]), "r"(a[1]), "r"(a[2]), "r"(a[3]), "r"(b0), "r"(b1));
}

// ---------------------------------------------------------------------------
// HGEMM (R14-measured-best config):  C[M,N] = A[M,1024] * W[N,1024]^T.
// 128x128x64 tiles, 128 threads (4 warps, warp tile 64x64), 3-stage cp.async,
// register-double-buffered fragments.  Rows padded to 72 halfs (144 B).
// MODE 1: QKV — fused RMSNorm + RoPE on q,k; fp16 out.   MODE 2: proj +bias,
// fp16 out at s2t rows.   MODE 3: proj +bias, fp32 out at t2s rows.
// ---------------------------------------------------------------------------
#define ROWB      144u
#define STG_A     18432u          // 128 rows * 144 B
#define STG_BYTES 36864u          // A + B
#define GSMEM     110592u         // 3 stages

template<int MODE>
__global__ __launch_bounds__(128, 2)
void hgemm(const unsigned short* __restrict__ A, const unsigned short* __restrict__ W,
           void* __restrict__ Cout, const float* __restrict__ bias, int Ntot,
           const float* __restrict__ qg, const float* __restrict__ kg,
           int seqlen, const float2* __restrict__ rope)
{
    extern __shared__ __align__(128) char smem[];
    const uint32_t sbase = su32(smem);
    const int tid  = threadIdx.x;
    const int lane = tid & 31;
    const int wid  = tid >> 5;
    const int m0 = blockIdx.y * 128;
    const int n0 = blockIdx.x * 128;
    const int wm = (wid >> 1) * 64;
    const int wn = (wid & 1) * 64;

    const int lg = tid & 7;
    const int lr = tid >> 3;          // 0..15
    const unsigned short* gA = A + (size_t)(m0 + lr) * 1024 + lg * 8;
    const unsigned short* gB = W + (size_t)(n0 + lr) * 1024 + lg * 8;
    const uint32_t sOff = (uint32_t)(lr * ROWB + lg * 16);

#define LOAD_STAGE(kt, slot)                                                  \
    {                                                                         \
        const uint32_t sa = sbase + (uint32_t)(slot) * STG_BYTES + sOff;      \
        const uint32_t sb = sa + STG_A;                                       \
        const size_t go = (size_t)(kt) * 64;                                  \
        _Pragma("unroll")                                                     \
        for (int i = 0; i < 8; i++) {                                         \
            cp_async16(sa + i * 2304u, gA + go + (size_t)(16 * i) * 1024);    \
            cp_async16(sb + i * 2304u, gB + go + (size_t)(16 * i) * 1024);    \
        }                                                                     \
        asm volatile("cp.async.commit_group;" ::: "memory");                  \
    }

    float c[4][8][4];
#pragma unroll
    for (int mt = 0; mt < 4; mt++)
#pragma unroll
        for (int nt = 0; nt < 8; nt++)
#pragma unroll
            for (int i = 0; i < 4; i++) c[mt][nt][i] = 0.f;

    LOAD_STAGE(0, 0);
    LOAD_STAGE(1, 1);

    const uint32_t aRow = (uint32_t)(wm + (lane & 15));
    const uint32_t aCol = (uint32_t)(((lane >> 4) & 1) * 16);
    const uint32_t bRow = (uint32_t)(wn + ((lane >> 4) << 3) + (lane & 7));
    const uint32_t bCol = (uint32_t)(((lane >> 3) & 1) * 16);

    for (int kt = 0; kt < 16; kt++) {
        asm volatile("cp.async.wait_group 1;" ::: "memory");
        __syncthreads();
        if (kt + 2 < 16) {
            LOAD_STAGE(kt + 2, (kt + 2) % 3);
        } else {
            asm volatile("cp.async.commit_group;" ::: "memory");
        }

        const uint32_t stA = sbase + (uint32_t)(kt % 3) * STG_BYTES;
        const uint32_t stB = stA + STG_A;

        uint32_t a[2][4][4], b[2][4][4];
#pragma unroll
        for (int mt = 0; mt < 4; mt++)
            ldsm4(a[0][mt], stA + (aRow + mt * 16) * ROWB + aCol);
#pragma unroll
        for (int np = 0; np < 4; np++)
            ldsm4(b[0][np], stB + (bRow + np * 16) * ROWB + bCol);

#pragma unroll
        for (int ks = 0; ks < 4; ks++) {
            const int cur = ks & 1, nxt = cur ^ 1;
            if (ks < 3) {
#pragma unroll
                for (int mt = 0; mt < 4; mt++)
                    ldsm4(a[nxt][mt],
                          stA + (aRow + mt * 16) * ROWB + (ks + 1) * 32 + aCol);
#pragma unroll
                for (int np = 0; np < 4; np++)
                    ldsm4(b[nxt][np],
                          stB + (bRow + np * 16) * ROWB + (ks + 1) * 32 + bCol);
            }
#pragma unroll
            for (int mt = 0; mt < 4; mt++)
#pragma unroll
                for (int np = 0; np < 4; np++) {
                    mma16816(c[mt][2 * np],     a[cur][mt], b[cur][np][0], b[cur][np][1]);
                    mma16816(c[mt][2 * np + 1], a[cur][mt], b[cur][np][2], b[cur][np][3]);
                }
        }
    }
#undef LOAD_STAGE

    const int grp = lane >> 2;
    const int qd  = (lane & 3) * 2;

    if (MODE == 1) {
        __half* C = (__half*)Cout;
        const int comp = n0 >> 10;
        if (comp == 2) {
#pragma unroll
            for (int mt = 0; mt < 4; mt++) {
                const int r0 = m0 + wm + mt * 16 + grp;
#pragma unroll
                for (int nt = 0; nt < 8; nt++) {
                    const int cn = n0 + wn + nt * 8 + qd;
                    *(__half2*)(C + (size_t)r0 * Ntot + cn) =
                        __floats2half2_rn(c[mt][nt][0], c[mt][nt][1]);
                    *(__half2*)(C + (size_t)(r0 + 8) * Ntot + cn) =
                        __floats2half2_rn(c[mt][nt][2], c[mt][nt][3]);
                }
            }
        } else {
            const float* g = comp ? kg : qg;
            float2 gv[8];
#pragma unroll
            for (int nt = 0; nt < 8; nt++)
                gv[nt] = *(const float2*)(g + nt * 8 + qd);
#pragma unroll
            for (int mt = 0; mt < 4; mt++) {
                const int r0 = m0 + wm + mt * 16 + grp;
                float ss0 = 0.f, ss1 = 0.f;
#pragma unroll
                for (int nt = 0; nt < 8; nt++) {
                    ss0 = fmaf(c[mt][nt][0], c[mt][nt][0], ss0);
                    ss0 = fmaf(c[mt][nt][1], c[mt][nt][1], ss0);
                    ss1 = fmaf(c[mt][nt][2], c[mt][nt][2], ss1);
                    ss1 = fmaf(c[mt][nt][3], c[mt][nt][3], ss1);
                }
                ss0 += __shfl_xor_sync(0xffffffffu, ss0, 1);
                ss0 += __shfl_xor_sync(0xffffffffu, ss0, 2);
                ss1 += __shfl_xor_sync(0xffffffffu, ss1, 1);
                ss1 += __shfl_xor_sync(0xffffffffu, ss1, 2);
                const float inv0 = rsqrtf(ss0 * (1.0f / 64.0f) + 1e-6f);
                const float inv1 = rsqrtf(ss1 * (1.0f / 64.0f) + 1e-6f);
                const float2* rp0 = rope + (r0 % seqlen) * 32 + (lane & 3);
                const float2* rp1 = rope + ((r0 + 8) % seqlen) * 32 + (lane & 3);
#pragma unroll
                for (int nt = 0; nt < 8; nt++) {
                    const float2 cs0 = rp0[nt * 4];
                    const float2 cs1 = rp1[nt * 4];
                    const float v0 = c[mt][nt][0] * inv0 * gv[nt].x;
                    const float v1 = c[mt][nt][1] * inv0 * gv[nt].y;
                    const float w0 = c[mt][nt][2] * inv1 * gv[nt].x;
                    const float w1 = c[mt][nt][3] * inv1 * gv[nt].y;
                    const int cn = n0 + wn + nt * 8 + qd;
                    *(__half2*)(C + (size_t)r0 * Ntot + cn) =
                        __floats2half2_rn(v0 * cs0.x - v1 * cs0.y,
                                          v1 * cs0.x + v0 * cs0.y);
                    *(__half2*)(C + (size_t)(r0 + 8) * Ntot + cn) =
                        __floats2half2_rn(w0 * cs1.x - w1 * cs1.y,
                                          w1 * cs1.x + w0 * cs1.y);
                }
            }
        }
    } else if (MODE == 2) {
        __half2* C = (__half2*)Cout;
#pragma unroll
        for (int mt = 0; mt < 4; mt++) {
            const int r0 = m0 + wm + mt * 16 + grp;
#pragma unroll
            for (int hf = 0; hf < 2; hf++) {
                const int r = r0 + 8 * hf;
                const int b = r / 5280;
                const int f = (r % 5280) / 220;
                const int p = r % 220;
                const int rt = (b * 220 + p) * 24 + f;
#pragma unroll
                for (int nt = 0; nt < 8; nt++) {
                    const int cn = n0 + wn + nt * 8 + qd;
                    const float x0 = c[mt][nt][2 * hf]     + bias[cn];
                    const float x1 = c[mt][nt][2 * hf + 1] + bias[cn + 1];
                    C[(size_t)rt * 512 + cn / 2] = __floats2half2_rn(x0, x1);
                }
            }
        }
    } else {
        float* C = (float*)Cout;
#pragma unroll
        for (int mt = 0; mt < 4; mt++) {
            const int r0 = m0 + wm + mt * 16 + grp;
#pragma unroll
            for (int hf = 0; hf < 2; hf++) {
                const int r = r0 + 8 * hf;
                const int f = r % 24;
                const int p = (r % 5280) / 24;
                const int b = r / 5280;
                const int rs = (b * 24 + f) * 220 + p;
#pragma unroll
                for (int nt = 0; nt < 8; nt++) {
                    const int cn = n0 + wn + nt * 8 + qd;
                    *(float2*)(C + (size_t)rs * Ntot + cn) =
                        make_float2(c[mt][nt][2 * hf]     + bias[cn],
                                    c[mt][nt][2 * hf + 1] + bias[cn + 1]);
                }
            }
        }
    }
}

// ---------------------------------------------------------------------------
// fp32 -> fp16 conversions; block 8192 of cvt_weights also fills RoPE table.
// ---------------------------------------------------------------------------
__device__ __forceinline__ uint2 cvt4(float4 v)
{
    union { __half2 h[2]; uint2 u; } p;
    p.h[0] = __floats2half2_rn(v.x, v.y);
    p.h[1] = __floats2half2_rn(v.z, v.w);
    return p.u;
}
__global__ void cvt_half(const float4* __restrict__ s, uint2* __restrict__ d, int n4)
{
    const int i = blockIdx.x * 256 + threadIdx.x;
    if (i < n4) d[i] = cvt4(s[i]);
}
__global__ void cvt_weights(const float4* __restrict__ w0, const float4* __restrict__ w1,
                            const float4* __restrict__ w2, const float4* __restrict__ w3,
                            uint2* __restrict__ d, float2* __restrict__ rope)
{
    if (blockIdx.x == 8192) {
        for (int idx = threadIdx.x; idx < 7040; idx += 256) {
            const int pos = idx >> 5, j = idx & 31;
            const float theta = exp2f((float)j * (-13.287712379549449f / 32.0f));
            float s, c;
            sincosf((float)pos * theta, &s, &c);
            rope[idx] = make_float2(c, s);
        }
        return;
    }
    const int i = blockIdx.x * 256 + threadIdx.x;
    float4 v;
    if (i < 786432)       v = w0[i];
    else if (i < 1048576) v = w1[i - 786432];
    else if (i < 1835008) v = w2[i - 1048576];
    else                  v = w3[i - 1835008];
    d[i] = cvt4(v);
}

// ---------------------------------------------------------------------------
// Spatial attention (S=220) — tensor-core flash kernel, 2 CTAs/SM.
// Grid (16 heads, 96 seqs); internal loop over 4 q-blocks of 64 so K/V are
// staged ONCE per (h,n) instead of 4x.  Q(qb+1) prefetched via cp.async
// overlapped with softmax+PV of qb.
// smem: Q 64x72, K 224x72 (rows 220-223 zero), V 224x72, S/P 64x232 (fp16).
// ---------------------------------------------------------------------------
#define AQ_STR 72
#define AS_STR 232
#define SM_Q   0u
#define SM_K   4608u
#define SM_V   20736u
#define SM_S   36864u
#define ATTN_SMEM 103424u

__global__ __launch_bounds__(256, 2)
void attn_spatial(const unsigned short* __restrict__ qkv,
                  unsigned short* __restrict__ out)
{
    extern __shared__ __align__(128) char smraw[];
    __half* sm = (__half*)smraw;
    const uint32_t sbase = su32(sm);
    const int h  = blockIdx.x;
    const int n  = blockIdx.y;
    const int tid = threadIdx.x;
    const int lane = tid & 31;
    const int w = tid >> 5;

    const __half* base = (const __half*)qkv + (size_t)n * 220 * 3072 + h * 64;

    const int jr = tid >> 2;          // 0..63
    const int jc = tid & 3;           // granules jc and jc+4 (16B each)

    // ---- stage K, V once (rows < 220; 220-223 zeroed) + Q(qb=0) ----
    {
#pragma unroll
        for (int rr = 0; rr < 4; rr++) {
            const int s = jr + rr * 64;   // 0..255
            if (s < 220) {
                const uint32_t kd = sbase + (SM_K + s * AQ_STR) * 2;
                const uint32_t vd = sbase + (SM_V + s * AQ_STR) * 2;
                const __half* ks = base + (size_t)s * 3072 + 1024;
                const __half* vs = base + (size_t)s * 3072 + 2048;
                cp_async16(kd + jc * 16,       ks + jc * 8);
                cp_async16(kd + (jc + 4) * 16, ks + (jc + 4) * 8);
                cp_async16(vd + jc * 16,       vs + jc * 8);
                cp_async16(vd + (jc + 4) * 16, vs + (jc + 4) * 8);
            }
        }
        if (tid < 64) {
            const int row = 220 + (tid >> 4);
            const int rem = tid & 15;
            const uint32_t off = (rem < 8) ? (SM_K + row * AQ_STR)
                                           : (SM_V + row * AQ_STR);
            *(uint4*)(sm + off + (rem & 7) * 8) = make_uint4(0, 0, 0, 0);
        }
        // Q block 0: rows jr (all < 220)
        const uint32_t qs = sbase + (SM_Q + jr * AQ_STR) * 2;
        cp_async16(qs + jc * 16,       base + (size_t)jr * 3072 + jc * 8);
        cp_async16(qs + (jc + 4) * 16, base + (size_t)jr * 3072 + (jc + 4) * 8);
        asm volatile("cp.async.commit_group;" ::: "memory");
        asm volatile("cp.async.wait_group 0;" ::: "memory");
    }
    __syncthreads();

    const int grp = lane >> 2;
    const int qd  = (lane & 3) * 2;

    for (int qb = 0; qb < 4; qb++) {
        // ---- score GEMM: S[64][224] = Q @ K^T  (warps 0-6: 32 cols each) ----
        if (w < 7) {
            const int n0 = w * 32;
            float c[4][4][4];
#pragma unroll
            for (int mt = 0; mt < 4; mt++)
#pragma unroll
                for (int nt = 0; nt < 4; nt++)
#pragma unroll
                    for (int i = 0; i < 4; i++) c[mt][nt][i] = 0.f;

            const uint32_t aRow = (uint32_t)(lane & 15);
            const uint32_t aCol = (uint32_t)(((lane >> 4) & 1) * 16);
            const uint32_t bRow = (uint32_t)(n0 + ((lane >> 4) << 3) + (lane & 7));
            const uint32_t bCol = (uint32_t)(((lane >> 3) & 1) * 16);
            const uint32_t qb0 = sbase + SM_Q * 2;
            const uint32_t kb0 = sbase + SM_K * 2;

#pragma unroll
            for (int ks = 0; ks < 4; ks++) {
                uint32_t a[4][4], b[2][4];
#pragma unroll
                for (int mt = 0; mt < 4; mt++)
                    ldsm4(a[mt], qb0 + (aRow + mt * 16) * (AQ_STR * 2) + ks * 32 + aCol);
#pragma unroll
                for (int nh = 0; nh < 2; nh++)
                    ldsm4(b[nh], kb0 + (bRow + nh * 16) * (AQ_STR * 2) + ks * 32 + bCol);
#pragma unroll
                for (int mt = 0; mt < 4; mt++)
#pragma unroll
                    for (int nh = 0; nh < 2; nh++) {
                        mma16816(c[mt][2 * nh],     a[mt], b[nh][0], b[nh][1]);
                        mma16816(c[mt][2 * nh + 1], a[mt], b[nh][2], b[nh][3]);
                    }
            }
            __half* sS = sm + SM_S;
#pragma unroll
            for (int mt = 0; mt < 4; mt++) {
                const int r0 = mt * 16 + grp;
#pragma unroll
                for (int nt = 0; nt < 4; nt++) {
                    const int cn = n0 + nt * 8 + qd;
                    *(__half2*)(sS + r0 * AS_STR + cn) =
                        __floats2half2_rn(c[mt][nt][0], c[mt][nt][1]);
                    *(__half2*)(sS + (r0 + 8) * AS_STR + cn) =
                        __floats2half2_rn(c[mt][nt][2], c[mt][nt][3]);
                }
            }
        }
        __syncthreads();

        // ---- prefetch Q(qb+1) (sQ is dead now; overlaps softmax + PV) ----
        if (qb < 3) {
            int qr = (qb + 1) * 64 + jr;
            if (qr > 219) qr = 219;
            const uint32_t qs = sbase + (SM_Q + jr * AQ_STR) * 2;
            cp_async16(qs + jc * 16,       base + (size_t)qr * 3072 + jc * 8);
            cp_async16(qs + (jc + 4) * 16, base + (size_t)qr * 3072 + (jc + 4) * 8);
            asm volatile("cp.async.commit_group;" ::: "memory");
        }

        // ---- softmax over cols [0,220); cols [220,224) -> 0 ----
        {
            __half* sS = sm + SM_S;
#pragma unroll
            for (int i = 0; i < 8; i++) {
                const int r = w * 8 + i;
                __half* row = sS + r * AS_STR;
                float v[7];
                float mx = -1e30f;
#pragma unroll
                for (int j = 0; j < 7; j++) {
                    const int cidx = lane + 32 * j;
                    v[j] = (cidx < 220) ? __half2float(row[cidx]) : -1e30f;
                    mx = fmaxf(mx, v[j]);
                }
#pragma unroll
                for (int o = 16; o > 0; o >>= 1)
                    mx = fmaxf(mx, __shfl_xor_sync(0xffffffffu, mx, o));
                float sum = 0.f;
#pragma unroll
                for (int j = 0; j < 7; j++) {
                    v[j] = (lane + 32 * j < 220) ? __expf(0.125f * (v[j] - mx)) : 0.f;
                    sum += v[j];
                }
#pragma unroll
                for (int o = 16; o > 0; o >>= 1)
                    sum += __shfl_xor_sync(0xffffffffu, sum, o);
                const float isum = 1.0f / sum;
#pragma unroll
                for (int j = 0; j < 7; j++)
                    row[lane + 32 * j] = __float2half_rn(v[j] * isum);
            }
        }
        __syncthreads();

        // ---- PV GEMM: O[64][64] = P[64][224] @ V[224][64] ----
        {
            const int wm2 = (w >> 2) * 32;
            const int wn2 = (w & 3) * 16;
            float c2[2][2][4];
#pragma unroll
            for (int mt = 0; mt < 2; mt++)
#pragma unroll
                for (int nt = 0; nt < 2; nt++)
#pragma unroll
                    for (int i = 0; i < 4; i++) c2[mt][nt][i] = 0.f;

            const uint32_t pb0 = sbase + SM_S * 2;
            const uint32_t vb0 = sbase + SM_V * 2;
            const uint32_t aRow2 = (uint32_t)(wm2 + (lane & 15));
            const uint32_t aCol2 = (uint32_t)(((lane >> 4) & 1) * 16);
            const uint32_t tRow = (uint32_t)(((lane >> 3) & 1) * 8 + (lane & 7));
            const uint32_t tCol = (uint32_t)((wn2 + ((lane >> 4) & 1) * 8) * 2);

#pragma unroll
            for (int ks = 0; ks < 14; ks++) {
                uint32_t a[2][4], b[4];
#pragma unroll
                for (int mt = 0; mt < 2; mt++)
                    ldsm4(a[mt], pb0 + (aRow2 + mt * 16) * (AS_STR * 2) + ks * 32 + aCol2);
                ldsm4t(b, vb0 + (ks * 16 + tRow) * (AQ_STR * 2) + tCol);
#pragma unroll
                for (int mt = 0; mt < 2; mt++) {
                    mma16816(c2[mt][0], a[mt], b[0], b[1]);
                    mma16816(c2[mt][1], a[mt], b[2], b[3]);
                }
            }

#pragma unroll
            for (int mt = 0; mt < 2; mt++) {
#pragma unroll
                for (int hf = 0; hf < 2; hf++) {
                    const int rl = wm2 + mt * 16 + grp + 8 * hf;
                    const int qr = qb * 64 + rl;
                    if (qr < 220) {
                        __half* op = (__half*)out + ((size_t)n * 220 + qr) * 1024
                                   + h * 64 + wn2 + qd;
                        *(__half2*)op = __floats2half2_rn(c2[mt][0][2 * hf],
                                                          c2[mt][0][2 * hf + 1]);
                        *(__half2*)(op + 8) = __floats2half2_rn(c2[mt][1][2 * hf],
                                                                c2[mt][1][2 * hf + 1]);
                    }
                }
            }
        }

        if (qb < 3) {
            asm volatile("cp.async.wait_group 0;" ::: "memory");
            __syncthreads();   // Q(qb+1) landed; sS free for next score GEMM
        }
    }
}

// ---------------------------------------------------------------------------
// Temporal attention (S=24) — scalar kernel (unchanged, known-good).
// ---------------------------------------------------------------------------
__global__ __launch_bounds__(256)
void attn_kernel(const unsigned short* __restrict__ qkv,
                 unsigned short* __restrict__ out, int S)
{
    extern __shared__ __align__(16) char smraw[];
    const int h = blockIdx.x;
    const int n = blockIdx.y;
    const int tid = threadIdx.x;
    const int w = tid >> 5;
    const int lane = tid & 31;

    float*  sP = (float*)smraw;
    float*  sQ = sP + 8 * S;
    __half* sK = (__half*)(sQ + 512);
    __half* sV = sK + S * 66;

    const __half* base = (const __half*)qkv + (size_t)n * S * 3072 + h * 64;
    for (int idx = tid; idx < S * 32; idx += 256) {
        const int s = idx >> 5, j = idx & 31;
        ((uint32_t*)(sK + s * 66))[j] =
            ((const uint32_t*)(base + (size_t)s * 3072 + 1024))[j];
        ((uint32_t*)(sV + s * 66))[j] =
            ((const uint32_t*)(base + (size_t)s * 3072 + 2048))[j];
    }
    __syncthreads();

    for (int r = w; r < S; r += 8) {
        {
            const __half2 hq = *(const __half2*)(base + (size_t)r * 3072 + 2 * lane);
            const float2 q2 = __half22float2(hq);
            sQ[w * 64 + 2 * lane]     = q2.x;
            sQ[w * 64 + 2 * lane + 1] = q2.y;
        }
        __syncwarp();
        const float* qr = sQ + w * 64;

        float sc[7];
        float mx = -1e30f;
        int cnt = 0;
        for (int s = lane; s < S; s += 32) {
            const uint32_t* kr = (const uint32_t*)(sK + s * 66);
            float d0 = 0.f, d1 = 0.f, d2 = 0.f, d3 = 0.f;
#pragma unroll
            for (int t = 0; t < 16; t++) {
                const float4 q4 = *(const float4*)(qr + 4 * t);
                const uint32_t ka = kr[2 * t];
                const uint32_t kb = kr[2 * t + 1];
                const float2 k0 = __half22float2(*(const __half2*)&ka);
                const float2 k1 = __half22float2(*(const __half2*)&kb);
                d0 = fmaf(q4.x, k0.x, d0);
                d1 = fmaf(q4.y, k0.y, d1);
                d2 = fmaf(q4.z, k1.x, d2);
                d3 = fmaf(q4.w, k1.y, d3);
            }
            const float dot = ((d0 + d1) + (d2 + d3)) * 0.125f;
            sc[cnt++] = dot;
            mx = fmaxf(mx, dot);
        }
#pragma unroll
        for (int o = 16; o > 0; o >>= 1) mx = fmaxf(mx, __shfl_xor_sync(0xffffffffu, mx, o));
        float sum = 0.f;
#pragma unroll
        for (int i = 0; i < 7; i++)
            if (i < cnt) { sc[i] = __expf(sc[i] - mx); sum += sc[i]; }
#pragma unroll
        for (int o = 16; o > 0; o >>= 1) sum += __shfl_xor_sync(0xffffffffu, sum, o);
        const float isum = 1.0f / sum;
        {
            int i = 0;
            for (int s = lane; s < S; s += 32) sP[w * S + s] = sc[i++] * isum;
        }
        __syncwarp();

        float a0 = 0.f, a1 = 0.f, a2 = 0.f, a3 = 0.f;
        float b0 = 0.f, b1 = 0.f, b2 = 0.f, b3 = 0.f;
        const float* pw = sP + w * S;
        const __half* v0p = sV + lane;
        const __half* v1p = sV + lane + 32;
        for (int s = 0; s < S; s += 4) {
            const float p0 = pw[s],     p1 = pw[s + 1];
            const float p2 = pw[s + 2], p3 = pw[s + 3];
            a0 = fmaf(p0, __half2float(v0p[(s)     * 66]), a0);
            b0 = fmaf(p0, __half2float(v1p[(s)     * 66]), b0);
            a1 = fmaf(p1, __half2float(v0p[(s + 1) * 66]), a1);
            b1 = fmaf(p1, __half2float(v1p[(s + 1) * 66]), b1);
            a2 = fmaf(p2, __half2float(v0p[(s + 2) * 66]), a2);
            b2 = fmaf(p2, __half2float(v1p[(s + 2) * 66]), b2);
            a3 = fmaf(p3, __half2float(v0p[(s + 3) * 66]), a3);
            b3 = fmaf(p3, __half2float(v1p[(s + 3) * 66]), b3);
        }
        __half* op = (__half*)(out + ((size_t)n * S + r) * 1024 + h * 64);
        op[lane]      = __float2half_rn((a0 + a1) + (a2 + a3));
        op[lane + 32] = __float2half_rn((b0 + b1) + (b2 + b3));
        __syncwarp();
    }
}

// ---------------------------------------------------------------------------
// Orchestration (graph-capturable: kernel launches only).
// Launch list: 0 cvt_half, 1 cvt_weights(+rope), 2 hgemm<1>,
//              3 attn_spatial (ncu capture slot), ...
// ---------------------------------------------------------------------------
extern "C" void kernel_launch(void* const* d_in, const int* in_sizes, int n_in,
                              void* d_out, int out_size)
{
    (void)in_sizes; (void)n_in; (void)out_size;
    const float* x       = (const float*)d_in[0];
    const float* w_sqkv  = (const float*)d_in[1];
    const float* w_sproj = (const float*)d_in[2];
    const float* b_sproj = (const float*)d_in[3];
    const float* w_tqkv  = (const float*)d_in[4];
    const float* w_tproj = (const float*)d_in[5];
    const float* b_tproj = (const float*)d_in[6];
    const float* sqg     = (const float*)d_in[7];
    const float* skg     = (const float*)d_in[8];
    const float* tqg     = (const float*)d_in[9];
    const float* tkg     = (const float*)d_in[10];
    float* out = (float*)d_out;

    unsigned short *qkv16, *hX, *hB, *hW;
    float2* rope;
    cudaGetSymbolAddress((void**)&qkv16, g_qkv);
    cudaGetSymbolAddress((void**)&rope, g_rope);
    cudaGetSymbolAddress((void**)&hX, g_halfX);
    cudaGetSymbolAddress((void**)&hB, g_halfB);
    cudaGetSymbolAddress((void**)&hW, g_halfW);

    unsigned short* wQS = hW;
    unsigned short* wPS = hW + 3145728;
    unsigned short* wQT = hW + 4194304;
    unsigned short* wPT = hW + 7340032;

    const size_t smemT = (size_t)(8 * 24) * 4 + 2048 + (size_t)(2 * 24 * 66) * 2 + 64;
    cudaFuncSetAttribute((const void*)attn_spatial,
                         cudaFuncAttributeMaxDynamicSharedMemorySize, (int)ATTN_SMEM);
    cudaFuncSetAttribute((const void*)attn_kernel,
                         cudaFuncAttributeMaxDynamicSharedMemorySize, (int)smemT);
    cudaFuncSetAttribute((const void*)hgemm<1>,
                         cudaFuncAttributeMaxDynamicSharedMemorySize, (int)GSMEM);
    cudaFuncSetAttribute((const void*)hgemm<2>,
                         cudaFuncAttributeMaxDynamicSharedMemorySize, (int)GSMEM);
    cudaFuncSetAttribute((const void*)hgemm<3>,
                         cudaFuncAttributeMaxDynamicSharedMemorySize, (int)GSMEM);

    dim3 blk(256);
    const int M = MROWS;

    // ---- prep (launch indices 0..1) ----
    cvt_half<<<21120, blk>>>((const float4*)x, (uint2*)hX, 5406720);
    cvt_weights<<<8193, blk>>>((const float4*)w_sqkv, (const float4*)w_sproj,
                               (const float4*)w_tqkv, (const float4*)w_tproj,
                               (uint2*)hW, rope);

    // ---- spatial block (attn_spatial at launch index 3 -> ncu capture) ----
    hgemm<1><<<dim3(24, M / 128), 128, GSMEM>>>(hX, wQS, qkv16, nullptr, 3072,
                                                sqg, skg, 220, rope);
    attn_spatial<<<dim3(16, 96), blk, ATTN_SMEM>>>(qkv16, hB);
    hgemm<2><<<dim3(8, M / 128), 128, GSMEM>>>(hB, wPS, hX, b_sproj, 1024,
                                               nullptr, nullptr, 0, nullptr);

    // ---- temporal block ----
    hgemm<1><<<dim3(24, M / 128), 128, GSMEM>>>(hX, wQT, qkv16, nullptr, 3072,
                                                tqg, tkg, 24, rope);
    attn_kernel<<<dim3(16, 880), blk, smemT>>>(qkv16, hB, 24);
    hgemm<3><<<dim3(8, M / 128), 128, GSMEM>>>(hB, wPT, out, b_tproj, 1024,
                                               nullptr, nullptr, 0, nullptr);
}

// round 17
// speedup vs baseline: 1.5062x; 1.5062x over previous
#include <cuda_runtime.h>
#include <cuda_fp16.h>
#include <cstdint>

// ---------------------------------------------------------------------------
// Problem constants:  x (4,5280,1024) fp32.  M = 21120 rows, K = 1024.
// Spatial attn: 96 seqs x 220 (tensor-core flash kernel, 2 CTAs/SM,
// grid (16,96,4)).  Temporal attn: 880 seqs x 24 (scalar kernel).
// GEMMs via mma.sync.m16n8k16 fp16, 128x128x64 tiles / 3-stage cp.async,
// 128 threads / 4 warps (warp tile 64x64, double-buffered frags).
// RMSNorm+RoPE fused into QKV epilogue (fp16 out); s2t / t2s permutes fused
// into the projection epilogues.   == R14 trunk (1632.8 us) + rope merge ==
// ---------------------------------------------------------------------------
#define MROWS 21120

// Scratch (static __device__ arrays — no allocation allowed)
__device__ __align__(1024) unsigned short g_qkv[64880640ull];   // qkv fp16
__device__ __align__(1024) float2         g_rope[7040];         // 220 x 32 (cos,sin)
__device__ __align__(1024) unsigned short g_halfX[21626880ull]; // x fp16 / temporal in
__device__ __align__(1024) unsigned short g_halfB[21626880ull]; // attn out fp16
__device__ __align__(1024) unsigned short g_halfW[8388608ull];  // weights fp16

// ---------------------------------------------------------------------------
// PTX helpers (base-target: cp.async sm_80, ldmatrix sm_75, mma sm_80)
// ---------------------------------------------------------------------------
__device__ __forceinline__ uint32_t su32(const void* p) {
    return (uint32_t)__cvta_generic_to_shared(p);
}
__device__ __forceinline__ void cp_async16(uint32_t s, const void* g) {
    asm volatile("cp.async.cg.shared.global [%0], [%1], 16;" :: "r"(s), "l"(g));
}
__device__ __forceinline__ void ldsm4(uint32_t* r, uint32_t a) {
    asm volatile("ldmatrix.sync.aligned.m8n8.x4.shared.b16 {%0,%1,%2,%3}, [%4];"
                 : "=r"(r[0]), "=r"(r[1]), "=r"(r[2]), "=r"(r[3]) : "r"(a));
}
__device__ __forceinline__ void ldsm4t(uint32_t* r, uint32_t a) {
    asm volatile("ldmatrix.sync.aligned.m8n8.x4.trans.shared.b16 {%0,%1,%2,%3}, [%4];"
                 : "=r"(r[0]), "=r"(r[1]), "=r"(r[2]), "=r"(r[3]) : "r"(a));
}
__device__ __forceinline__ void mma16816(float* c, const uint32_t* a,
                                         uint32_t b0, uint32_t b1) {
    asm volatile(
        "mma.sync.aligned.m16n8k16.row.col.f32.f16.f16.f32 "
        "{%0,%1,%2,%3}, {%4,%5,%6,%7}, {%8,%9}, {%0,%1,%2,%3};"
        : "+f"(c[0]), "+f"(c[1]), "+f"(c[2]), "+f"(c[3])
        : "r"(a[0]), "r"(a[1]), "r"(a[2]), "r"(a[3]), "r"(b0), "r"(b1));
}

// ---------------------------------------------------------------------------
// HGEMM:  C[M,N] = A[M,1024] * W[N,1024]^T, fp16 in / fp32 accum.
// 128x128x64 tiles, 128 threads (4 warps, warp tile 64x64), 3-stage cp.async,
// register-double-buffered fragments.  Rows padded to 72 halfs (144 B).
// MODE 1: QKV — fused RMSNorm + RoPE on q,k; fp16 out.   MODE 2: proj +bias,
// fp16 out at s2t rows.   MODE 3: proj +bias, fp32 out at t2s rows.
// ---------------------------------------------------------------------------
#define ROWB      144u
#define STG_A     18432u          // 128 rows * 144 B
#define STG_BYTES 36864u          // A + B
#define GSMEM     110592u         // 3 stages

template<int MODE>
__global__ __launch_bounds__(128, 2)
void hgemm(const unsigned short* __restrict__ A, const unsigned short* __restrict__ W,
           void* __restrict__ Cout, const float* __restrict__ bias, int Ntot,
           const float* __restrict__ qg, const float* __restrict__ kg,
           int seqlen, const float2* __restrict__ rope)
{
    extern __shared__ __align__(128) char smem[];
    const uint32_t sbase = su32(smem);
    const int tid  = threadIdx.x;
    const int lane = tid & 31;
    const int wid  = tid >> 5;
    const int m0 = blockIdx.y * 128;
    const int n0 = blockIdx.x * 128;
    const int wm = (wid >> 1) * 64;
    const int wn = (wid & 1) * 64;

    const int lg = tid & 7;
    const int lr = tid >> 3;          // 0..15
    const unsigned short* gA = A + (size_t)(m0 + lr) * 1024 + lg * 8;
    const unsigned short* gB = W + (size_t)(n0 + lr) * 1024 + lg * 8;
    const uint32_t sOff = (uint32_t)(lr * ROWB + lg * 16);

#define LOAD_STAGE(kt, slot)                                                  \
    {                                                                         \
        const uint32_t sa = sbase + (uint32_t)(slot) * STG_BYTES + sOff;      \
        const uint32_t sb = sa + STG_A;                                       \
        const size_t go = (size_t)(kt) * 64;                                  \
        _Pragma("unroll")                                                     \
        for (int i = 0; i < 8; i++) {                                         \
            cp_async16(sa + i * 2304u, gA + go + (size_t)(16 * i) * 1024);    \
            cp_async16(sb + i * 2304u, gB + go + (size_t)(16 * i) * 1024);    \
        }                                                                     \
        asm volatile("cp.async.commit_group;" ::: "memory");                  \
    }

    float c[4][8][4];
#pragma unroll
    for (int mt = 0; mt < 4; mt++)
#pragma unroll
        for (int nt = 0; nt < 8; nt++)
#pragma unroll
            for (int i = 0; i < 4; i++) c[mt][nt][i] = 0.f;

    LOAD_STAGE(0, 0);
    LOAD_STAGE(1, 1);

    const uint32_t aRow = (uint32_t)(wm + (lane & 15));
    const uint32_t aCol = (uint32_t)(((lane >> 4) & 1) * 16);
    const uint32_t bRow = (uint32_t)(wn + ((lane >> 4) << 3) + (lane & 7));
    const uint32_t bCol = (uint32_t)(((lane >> 3) & 1) * 16);

    for (int kt = 0; kt < 16; kt++) {
        asm volatile("cp.async.wait_group 1;" ::: "memory");
        __syncthreads();
        if (kt + 2 < 16) {
            LOAD_STAGE(kt + 2, (kt + 2) % 3);
        } else {
            asm volatile("cp.async.commit_group;" ::: "memory");
        }

        const uint32_t stA = sbase + (uint32_t)(kt % 3) * STG_BYTES;
        const uint32_t stB = stA + STG_A;

        uint32_t a[2][4][4], b[2][4][4];
#pragma unroll
        for (int mt = 0; mt < 4; mt++)
            ldsm4(a[0][mt], stA + (aRow + mt * 16) * ROWB + aCol);
#pragma unroll
        for (int np = 0; np < 4; np++)
            ldsm4(b[0][np], stB + (bRow + np * 16) * ROWB + bCol);

#pragma unroll
        for (int ks = 0; ks < 4; ks++) {
            const int cur = ks & 1, nxt = cur ^ 1;
            if (ks < 3) {
#pragma unroll
                for (int mt = 0; mt < 4; mt++)
                    ldsm4(a[nxt][mt],
                          stA + (aRow + mt * 16) * ROWB + (ks + 1) * 32 + aCol);
#pragma unroll
                for (int np = 0; np < 4; np++)
                    ldsm4(b[nxt][np],
                          stB + (bRow + np * 16) * ROWB + (ks + 1) * 32 + bCol);
            }
#pragma unroll
            for (int mt = 0; mt < 4; mt++)
#pragma unroll
                for (int np = 0; np < 4; np++) {
                    mma16816(c[mt][2 * np],     a[cur][mt], b[cur][np][0], b[cur][np][1]);
                    mma16816(c[mt][2 * np + 1], a[cur][mt], b[cur][np][2], b[cur][np][3]);
                }
        }
    }
#undef LOAD_STAGE

    const int grp = lane >> 2;
    const int qd  = (lane & 3) * 2;

    if (MODE == 1) {
        __half* C = (__half*)Cout;
        const int comp = n0 >> 10;
        if (comp == 2) {
#pragma unroll
            for (int mt = 0; mt < 4; mt++) {
                const int r0 = m0 + wm + mt * 16 + grp;
#pragma unroll
                for (int nt = 0; nt < 8; nt++) {
                    const int cn = n0 + wn + nt * 8 + qd;
                    *(__half2*)(C + (size_t)r0 * Ntot + cn) =
                        __floats2half2_rn(c[mt][nt][0], c[mt][nt][1]);
                    *(__half2*)(C + (size_t)(r0 + 8) * Ntot + cn) =
                        __floats2half2_rn(c[mt][nt][2], c[mt][nt][3]);
                }
            }
        } else {
            const float* g = comp ? kg : qg;
            float2 gv[8];
#pragma unroll
            for (int nt = 0; nt < 8; nt++)
                gv[nt] = *(const float2*)(g + nt * 8 + qd);
#pragma unroll
            for (int mt = 0; mt < 4; mt++) {
                const int r0 = m0 + wm + mt * 16 + grp;
                float ss0 = 0.f, ss1 = 0.f;
#pragma unroll
                for (int nt = 0; nt < 8; nt++) {
                    ss0 = fmaf(c[mt][nt][0], c[mt][nt][0], ss0);
                    ss0 = fmaf(c[mt][nt][1], c[mt][nt][1], ss0);
                    ss1 = fmaf(c[mt][nt][2], c[mt][nt][2], ss1);
                    ss1 = fmaf(c[mt][nt][3], c[mt][nt][3], ss1);
                }
                ss0 += __shfl_xor_sync(0xffffffffu, ss0, 1);
                ss0 += __shfl_xor_sync(0xffffffffu, ss0, 2);
                ss1 += __shfl_xor_sync(0xffffffffu, ss1, 1);
                ss1 += __shfl_xor_sync(0xffffffffu, ss1, 2);
                const float inv0 = rsqrtf(ss0 * (1.0f / 64.0f) + 1e-6f);
                const float inv1 = rsqrtf(ss1 * (1.0f / 64.0f) + 1e-6f);
                const float2* rp0 = rope + (r0 % seqlen) * 32 + (lane & 3);
                const float2* rp1 = rope + ((r0 + 8) % seqlen) * 32 + (lane & 3);
#pragma unroll
                for (int nt = 0; nt < 8; nt++) {
                    const float2 cs0 = rp0[nt * 4];
                    const float2 cs1 = rp1[nt * 4];
                    const float v0 = c[mt][nt][0] * inv0 * gv[nt].x;
                    const float v1 = c[mt][nt][1] * inv0 * gv[nt].y;
                    const float w0 = c[mt][nt][2] * inv1 * gv[nt].x;
                    const float w1 = c[mt][nt][3] * inv1 * gv[nt].y;
                    const int cn = n0 + wn + nt * 8 + qd;
                    *(__half2*)(C + (size_t)r0 * Ntot + cn) =
                        __floats2half2_rn(v0 * cs0.x - v1 * cs0.y,
                                          v1 * cs0.x + v0 * cs0.y);
                    *(__half2*)(C + (size_t)(r0 + 8) * Ntot + cn) =
                        __floats2half2_rn(w0 * cs1.x - w1 * cs1.y,
                                          w1 * cs1.x + w0 * cs1.y);
                }
            }
        }
    } else if (MODE == 2) {
        __half2* C = (__half2*)Cout;
#pragma unroll
        for (int mt = 0; mt < 4; mt++) {
            const int r0 = m0 + wm + mt * 16 + grp;
#pragma unroll
            for (int hf = 0; hf < 2; hf++) {
                const int r = r0 + 8 * hf;
                const int b = r / 5280;
                const int f = (r % 5280) / 220;
                const int p = r % 220;
                const int rt = (b * 220 + p) * 24 + f;
#pragma unroll
                for (int nt = 0; nt < 8; nt++) {
                    const int cn = n0 + wn + nt * 8 + qd;
                    const float x0 = c[mt][nt][2 * hf]     + bias[cn];
                    const float x1 = c[mt][nt][2 * hf + 1] + bias[cn + 1];
                    C[(size_t)rt * 512 + cn / 2] = __floats2half2_rn(x0, x1);
                }
            }
        }
    } else {
        float* C = (float*)Cout;
#pragma unroll
        for (int mt = 0; mt < 4; mt++) {
            const int r0 = m0 + wm + mt * 16 + grp;
#pragma unroll
            for (int hf = 0; hf < 2; hf++) {
                const int r = r0 + 8 * hf;
                const int f = r % 24;
                const int p = (r % 5280) / 24;
                const int b = r / 5280;
                const int rs = (b * 24 + f) * 220 + p;
#pragma unroll
                for (int nt = 0; nt < 8; nt++) {
                    const int cn = n0 + wn + nt * 8 + qd;
                    *(float2*)(C + (size_t)rs * Ntot + cn) =
                        make_float2(c[mt][nt][2 * hf]     + bias[cn],
                                    c[mt][nt][2 * hf + 1] + bias[cn + 1]);
                }
            }
        }
    }
}

// ---------------------------------------------------------------------------
// fp32 -> fp16 conversions; block 8192 of cvt_weights also fills RoPE table.
// ---------------------------------------------------------------------------
__device__ __forceinline__ uint2 cvt4(float4 v)
{
    union { __half2 h[2]; uint2 u; } p;
    p.h[0] = __floats2half2_rn(v.x, v.y);
    p.h[1] = __floats2half2_rn(v.z, v.w);
    return p.u;
}
__global__ void cvt_half(const float4* __restrict__ s, uint2* __restrict__ d, int n4)
{
    const int i = blockIdx.x * 256 + threadIdx.x;
    if (i < n4) d[i] = cvt4(s[i]);
}
__global__ void cvt_weights(const float4* __restrict__ w0, const float4* __restrict__ w1,
                            const float4* __restrict__ w2, const float4* __restrict__ w3,
                            uint2* __restrict__ d, float2* __restrict__ rope)
{
    if (blockIdx.x == 8192) {
        for (int idx = threadIdx.x; idx < 7040; idx += 256) {
            const int pos = idx >> 5, j = idx & 31;
            const float theta = exp2f((float)j * (-13.287712379549449f / 32.0f));
            float s, c;
            sincosf((float)pos * theta, &s, &c);
            rope[idx] = make_float2(c, s);
        }
        return;
    }
    const int i = blockIdx.x * 256 + threadIdx.x;
    float4 v;
    if (i < 786432)       v = w0[i];
    else if (i < 1048576) v = w1[i - 786432];
    else if (i < 1835008) v = w2[i - 1048576];
    else                  v = w3[i - 1835008];
    d[i] = cvt4(v);
}

// ---------------------------------------------------------------------------
// Spatial attention (S=220) — tensor-core flash kernel, 2 CTAs/SM.
// Grid (16 heads, 96 seqs, 4 q-blocks of 64).  256 threads (8 warps).
// smem: Q 64x72, K 224x72 (rows 220-223 zero), V 224x72, S/P 64x232 (fp16).
// Score GEMM M64 N224 K64 (7 warps x 32 cols); softmax; PV GEMM M64 N64 K224.
// (R14 trunk version — measured best.)
// ---------------------------------------------------------------------------
#define AQ_STR 72
#define AS_STR 232
#define SM_Q   0u
#define SM_K   4608u
#define SM_V   20736u
#define SM_S   36864u
#define ATTN_SMEM 103424u

__global__ __launch_bounds__(256, 2)
void attn_spatial(const unsigned short* __restrict__ qkv,
                  unsigned short* __restrict__ out)
{
    extern __shared__ __align__(128) char smraw[];
    __half* sm = (__half*)smraw;
    const uint32_t sbase = su32(sm);
    const int h  = blockIdx.x;
    const int n  = blockIdx.y;
    const int qb = blockIdx.z;
    const int tid = threadIdx.x;
    const int lane = tid & 31;
    const int w = tid >> 5;

    const __half* base = (const __half*)qkv + (size_t)n * 220 * 3072 + h * 64;

    {
        const int jr = tid >> 2;
        const int jc = tid & 3;
        int qr = qb * 64 + jr; if (qr > 219) qr = 219;
        const uint32_t qs = sbase + (SM_Q + jr * AQ_STR) * 2;
        cp_async16(qs + jc * 16,       base + (size_t)qr * 3072 + jc * 8);
        cp_async16(qs + (jc + 4) * 16, base + (size_t)qr * 3072 + (jc + 4) * 8);
#pragma unroll
        for (int rr = 0; rr < 4; rr++) {
            const int s = jr + rr * 64;
            if (s < 220) {
                const uint32_t kd = sbase + (SM_K + s * AQ_STR) * 2;
                const uint32_t vd = sbase + (SM_V + s * AQ_STR) * 2;
                const __half* ks = base + (size_t)s * 3072 + 1024;
                const __half* vs = base + (size_t)s * 3072 + 2048;
                cp_async16(kd + jc * 16,       ks + jc * 8);
                cp_async16(kd + (jc + 4) * 16, ks + (jc + 4) * 8);
                cp_async16(vd + jc * 16,       vs + jc * 8);
                cp_async16(vd + (jc + 4) * 16, vs + (jc + 4) * 8);
            }
        }
        if (tid < 64) {
            const int row = 220 + (tid >> 4);
            const int rem = tid & 15;
            const uint32_t off = (rem < 8) ? (SM_K + row * AQ_STR)
                                           : (SM_V + row * AQ_STR);
            *(uint4*)(sm + off + (rem & 7) * 8) = make_uint4(0, 0, 0, 0);
        }
        asm volatile("cp.async.commit_group;" ::: "memory");
        asm volatile("cp.async.wait_group 0;" ::: "memory");
    }
    __syncthreads();

    const int grp = lane >> 2;
    const int qd  = (lane & 3) * 2;

    if (w < 7) {
        const int n0 = w * 32;
        float c[4][4][4];
#pragma unroll
        for (int mt = 0; mt < 4; mt++)
#pragma unroll
            for (int nt = 0; nt < 4; nt++)
#pragma unroll
                for (int i = 0; i < 4; i++) c[mt][nt][i] = 0.f;

        const uint32_t aRow = (uint32_t)(lane & 15);
        const uint32_t aCol = (uint32_t)(((lane >> 4) & 1) * 16);
        const uint32_t bRow = (uint32_t)(n0 + ((lane >> 4) << 3) + (lane & 7));
        const uint32_t bCol = (uint32_t)(((lane >> 3) & 1) * 16);
        const uint32_t qb0 = sbase + SM_Q * 2;
        const uint32_t kb0 = sbase + SM_K * 2;

#pragma unroll
        for (int ks = 0; ks < 4; ks++) {
            uint32_t a[4][4], b[2][4];
#pragma unroll
            for (int mt = 0; mt < 4; mt++)
                ldsm4(a[mt], qb0 + (aRow + mt * 16) * (AQ_STR * 2) + ks * 32 + aCol);
#pragma unroll
            for (int nh = 0; nh < 2; nh++)
                ldsm4(b[nh], kb0 + (bRow + nh * 16) * (AQ_STR * 2) + ks * 32 + bCol);
#pragma unroll
            for (int mt = 0; mt < 4; mt++)
#pragma unroll
                for (int nh = 0; nh < 2; nh++) {
                    mma16816(c[mt][2 * nh],     a[mt], b[nh][0], b[nh][1]);
                    mma16816(c[mt][2 * nh + 1], a[mt], b[nh][2], b[nh][3]);
                }
        }
        __half* sS = sm + SM_S;
#pragma unroll
        for (int mt = 0; mt < 4; mt++) {
            const int r0 = mt * 16 + grp;
#pragma unroll
            for (int nt = 0; nt < 4; nt++) {
                const int cn = n0 + nt * 8 + qd;
                *(__half2*)(sS + r0 * AS_STR + cn) =
                    __floats2half2_rn(c[mt][nt][0], c[mt][nt][1]);
                *(__half2*)(sS + (r0 + 8) * AS_STR + cn) =
                    __floats2half2_rn(c[mt][nt][2], c[mt][nt][3]);
            }
        }
    }
    __syncthreads();

    {
        __half* sS = sm + SM_S;
#pragma unroll
        for (int i = 0; i < 8; i++) {
            const int r = w * 8 + i;
            __half* row = sS + r * AS_STR;
            float v[7];
            float mx = -1e30f;
#pragma unroll
            for (int j = 0; j < 7; j++) {
                const int cidx = lane + 32 * j;
                v[j] = (cidx < 220) ? __half2float(row[cidx]) : -1e30f;
                mx = fmaxf(mx, v[j]);
            }
#pragma unroll
            for (int o = 16; o > 0; o >>= 1)
                mx = fmaxf(mx, __shfl_xor_sync(0xffffffffu, mx, o));
            float sum = 0.f;
#pragma unroll
            for (int j = 0; j < 7; j++) {
                v[j] = (lane + 32 * j < 220) ? __expf(0.125f * (v[j] - mx)) : 0.f;
                sum += v[j];
            }
#pragma unroll
            for (int o = 16; o > 0; o >>= 1)
                sum += __shfl_xor_sync(0xffffffffu, sum, o);
            const float isum = 1.0f / sum;
#pragma unroll
            for (int j = 0; j < 7; j++)
                row[lane + 32 * j] = __float2half_rn(v[j] * isum);
        }
    }
    __syncthreads();

    {
        const int wm2 = (w >> 2) * 32;
        const int wn2 = (w & 3) * 16;
        float c2[2][2][4];
#pragma unroll
        for (int mt = 0; mt < 2; mt++)
#pragma unroll
            for (int nt = 0; nt < 2; nt++)
#pragma unroll
                for (int i = 0; i < 4; i++) c2[mt][nt][i] = 0.f;

        const uint32_t pb0 = sbase + SM_S * 2;
        const uint32_t vb0 = sbase + SM_V * 2;
        const uint32_t aRow2 = (uint32_t)(wm2 + (lane & 15));
        const uint32_t aCol2 = (uint32_t)(((lane >> 4) & 1) * 16);
        const uint32_t tRow = (uint32_t)(((lane >> 3) & 1) * 8 + (lane & 7));
        const uint32_t tCol = (uint32_t)((wn2 + ((lane >> 4) & 1) * 8) * 2);

#pragma unroll
        for (int ks = 0; ks < 14; ks++) {
            uint32_t a[2][4], b[4];
#pragma unroll
            for (int mt = 0; mt < 2; mt++)
                ldsm4(a[mt], pb0 + (aRow2 + mt * 16) * (AS_STR * 2) + ks * 32 + aCol2);
            ldsm4t(b, vb0 + (ks * 16 + tRow) * (AQ_STR * 2) + tCol);
#pragma unroll
            for (int mt = 0; mt < 2; mt++) {
                mma16816(c2[mt][0], a[mt], b[0], b[1]);
                mma16816(c2[mt][1], a[mt], b[2], b[3]);
            }
        }

#pragma unroll
        for (int mt = 0; mt < 2; mt++) {
#pragma unroll
            for (int hf = 0; hf < 2; hf++) {
                const int rl = wm2 + mt * 16 + grp + 8 * hf;
                const int qr = qb * 64 + rl;
                if (qr < 220) {
                    __half* op = (__half*)out + ((size_t)n * 220 + qr) * 1024
                               + h * 64 + wn2 + qd;
                    *(__half2*)op = __floats2half2_rn(c2[mt][0][2 * hf],
                                                      c2[mt][0][2 * hf + 1]);
                    *(__half2*)(op + 8) = __floats2half2_rn(c2[mt][1][2 * hf],
                                                            c2[mt][1][2 * hf + 1]);
                }
            }
        }
    }
}

// ---------------------------------------------------------------------------
// Temporal attention (S=24) — scalar kernel (unchanged, known-good).
// ---------------------------------------------------------------------------
__global__ __launch_bounds__(256)
void attn_kernel(const unsigned short* __restrict__ qkv,
                 unsigned short* __restrict__ out, int S)
{
    extern __shared__ __align__(16) char smraw[];
    const int h = blockIdx.x;
    const int n = blockIdx.y;
    const int tid = threadIdx.x;
    const int w = tid >> 5;
    const int lane = tid & 31;

    float*  sP = (float*)smraw;
    float*  sQ = sP + 8 * S;
    __half* sK = (__half*)(sQ + 512);
    __half* sV = sK + S * 66;

    const __half* base = (const __half*)qkv + (size_t)n * S * 3072 + h * 64;
    for (int idx = tid; idx < S * 32; idx += 256) {
        const int s = idx >> 5, j = idx & 31;
        ((uint32_t*)(sK + s * 66))[j] =
            ((const uint32_t*)(base + (size_t)s * 3072 + 1024))[j];
        ((uint32_t*)(sV + s * 66))[j] =
            ((const uint32_t*)(base + (size_t)s * 3072 + 2048))[j];
    }
    __syncthreads();

    for (int r = w; r < S; r += 8) {
        {
            const __half2 hq = *(const __half2*)(base + (size_t)r * 3072 + 2 * lane);
            const float2 q2 = __half22float2(hq);
            sQ[w * 64 + 2 * lane]     = q2.x;
            sQ[w * 64 + 2 * lane + 1] = q2.y;
        }
        __syncwarp();
        const float* qr = sQ + w * 64;

        float sc[7];
        float mx = -1e30f;
        int cnt = 0;
        for (int s = lane; s < S; s += 32) {
            const uint32_t* kr = (const uint32_t*)(sK + s * 66);
            float d0 = 0.f, d1 = 0.f, d2 = 0.f, d3 = 0.f;
#pragma unroll
            for (int t = 0; t < 16; t++) {
                const float4 q4 = *(const float4*)(qr + 4 * t);
                const uint32_t ka = kr[2 * t];
                const uint32_t kb = kr[2 * t + 1];
                const float2 k0 = __half22float2(*(const __half2*)&ka);
                const float2 k1 = __half22float2(*(const __half2*)&kb);
                d0 = fmaf(q4.x, k0.x, d0);
                d1 = fmaf(q4.y, k0.y, d1);
                d2 = fmaf(q4.z, k1.x, d2);
                d3 = fmaf(q4.w, k1.y, d3);
            }
            const float dot = ((d0 + d1) + (d2 + d3)) * 0.125f;
            sc[cnt++] = dot;
            mx = fmaxf(mx, dot);
        }
#pragma unroll
        for (int o = 16; o > 0; o >>= 1) mx = fmaxf(mx, __shfl_xor_sync(0xffffffffu, mx, o));
        float sum = 0.f;
#pragma unroll
        for (int i = 0; i < 7; i++)
            if (i < cnt) { sc[i] = __expf(sc[i] - mx); sum += sc[i]; }
#pragma unroll
        for (int o = 16; o > 0; o >>= 1) sum += __shfl_xor_sync(0xffffffffu, sum, o);
        const float isum = 1.0f / sum;
        {
            int i = 0;
            for (int s = lane; s < S; s += 32) sP[w * S + s] = sc[i++] * isum;
        }
        __syncwarp();

        float a0 = 0.f, a1 = 0.f, a2 = 0.f, a3 = 0.f;
        float b0 = 0.f, b1 = 0.f, b2 = 0.f, b3 = 0.f;
        const float* pw = sP + w * S;
        const __half* v0p = sV + lane;
        const __half* v1p = sV + lane + 32;
        for (int s = 0; s < S; s += 4) {
            const float p0 = pw[s],     p1 = pw[s + 1];
            const float p2 = pw[s + 2], p3 = pw[s + 3];
            a0 = fmaf(p0, __half2float(v0p[(s)     * 66]), a0);
            b0 = fmaf(p0, __half2float(v1p[(s)     * 66]), b0);
            a1 = fmaf(p1, __half2float(v0p[(s + 1) * 66]), a1);
            b1 = fmaf(p1, __half2float(v1p[(s + 1) * 66]), b1);
            a2 = fmaf(p2, __half2float(v0p[(s + 2) * 66]), a2);
            b2 = fmaf(p2, __half2float(v1p[(s + 2) * 66]), b2);
            a3 = fmaf(p3, __half2float(v0p[(s + 3) * 66]), a3);
            b3 = fmaf(p3, __half2float(v1p[(s + 3) * 66]), b3);
        }
        __half* op = (__half*)(out + ((size_t)n * S + r) * 1024 + h * 64);
        op[lane]      = __float2half_rn((a0 + a1) + (a2 + a3));
        op[lane + 32] = __float2half_rn((b0 + b1) + (b2 + b3));
        __syncwarp();
    }
}

// ---------------------------------------------------------------------------
// Orchestration (graph-capturable: kernel launches only).
// Launch list: 0 cvt_half, 1 cvt_weights(+rope), 2 hgemm<1>,
//              3 attn_spatial (ncu capture slot), ...
// ---------------------------------------------------------------------------
extern "C" void kernel_launch(void* const* d_in, const int* in_sizes, int n_in,
                              void* d_out, int out_size)
{
    (void)in_sizes; (void)n_in; (void)out_size;
    const float* x       = (const float*)d_in[0];
    const float* w_sqkv  = (const float*)d_in[1];
    const float* w_sproj = (const float*)d_in[2];
    const float* b_sproj = (const float*)d_in[3];
    const float* w_tqkv  = (const float*)d_in[4];
    const float* w_tproj = (const float*)d_in[5];
    const float* b_tproj = (const float*)d_in[6];
    const float* sqg     = (const float*)d_in[7];
    const float* skg     = (const float*)d_in[8];
    const float* tqg     = (const float*)d_in[9];
    const float* tkg     = (const float*)d_in[10];
    float* out = (float*)d_out;

    unsigned short *qkv16, *hX, *hB, *hW;
    float2* rope;
    cudaGetSymbolAddress((void**)&qkv16, g_qkv);
    cudaGetSymbolAddress((void**)&rope, g_rope);
    cudaGetSymbolAddress((void**)&hX, g_halfX);
    cudaGetSymbolAddress((void**)&hB, g_halfB);
    cudaGetSymbolAddress((void**)&hW, g_halfW);

    unsigned short* wQS = hW;
    unsigned short* wPS = hW + 3145728;
    unsigned short* wQT = hW + 4194304;
    unsigned short* wPT = hW + 7340032;

    const size_t smemT = (size_t)(8 * 24) * 4 + 2048 + (size_t)(2 * 24 * 66) * 2 + 64;
    cudaFuncSetAttribute((const void*)attn_spatial,
                         cudaFuncAttributeMaxDynamicSharedMemorySize, (int)ATTN_SMEM);
    cudaFuncSetAttribute((const void*)attn_kernel,
                         cudaFuncAttributeMaxDynamicSharedMemorySize, (int)smemT);
    cudaFuncSetAttribute((const void*)hgemm<1>,
                         cudaFuncAttributeMaxDynamicSharedMemorySize, (int)GSMEM);
    cudaFuncSetAttribute((const void*)hgemm<2>,
                         cudaFuncAttributeMaxDynamicSharedMemorySize, (int)GSMEM);
    cudaFuncSetAttribute((const void*)hgemm<3>,
                         cudaFuncAttributeMaxDynamicSharedMemorySize, (int)GSMEM);

    dim3 blk(256);
    const int M = MROWS;

    // ---- prep (launch indices 0..1) ----
    cvt_half<<<21120, blk>>>((const float4*)x, (uint2*)hX, 5406720);
    cvt_weights<<<8193, blk>>>((const float4*)w_sqkv, (const float4*)w_sproj,
                               (const float4*)w_tqkv, (const float4*)w_tproj,
                               (uint2*)hW, rope);

    // ---- spatial block (attn_spatial at launch index 3 -> ncu capture) ----
    hgemm<1><<<dim3(24, M / 128), 128, GSMEM>>>(hX, wQS, qkv16, nullptr, 3072,
                                                sqg, skg, 220, rope);
    attn_spatial<<<dim3(16, 96, 4), blk, ATTN_SMEM>>>(qkv16, hB);
    hgemm<2><<<dim3(8, M / 128), 128, GSMEM>>>(hB, wPS, hX, b_sproj, 1024,
                                               nullptr, nullptr, 0, nullptr);

    // ---- temporal block ----
    hgemm<1><<<dim3(24, M / 128), 128, GSMEM>>>(hX, wQT, qkv16, nullptr, 3072,
                                                tqg, tkg, 24, rope);
    attn_kernel<<<dim3(16, 880), blk, smemT>>>(qkv16, hB, 24);
    hgemm<3><<<dim3(8, M / 128), 128, GSMEM>>>(hB, wPT, out, b_tproj, 1024,
                                               nullptr, nullptr, 0, nullptr);
}